// round 8
// baseline (speedup 1.0000x reference)
#include <cuda_runtime.h>
#include <cuda_bf16.h>
#include <cstdint>

#define B_ 8192
#define D_ 2048
#define C_ 1000
#define EPS32 1.1920929e-7f

// ---------------- scratch (no allocations allowed) ----------------
__device__ __nv_bfloat16 g_z[B_ * (size_t)D_];   // z = feature + eps, bf16
__device__ __nv_bfloat16 g_w[C_ * (size_t)D_];   // cls_w, bf16 [C, D] K-major
__device__ float g_wsum[D_];                     // column sums of w (over C)
__device__ float g_bsum;                         // sum of cls_b
__device__ float g_rowsum[B_];                   // rowsum[b] = z.wsum + bsum

// NOTE: g_wsum / g_bsum are zero at module load, and the GEMM kernel (last in
// the launch chain) re-zeroes them for the next graph replay.

// ---------------- kernel 1: wsum[k] = sum_c bf16(w[c,k]) ; bsum -------------
// 8 k-chunks x 25 c-chunks = 200 blocks x 256 thr; 40 independent loads/thread
__global__ __launch_bounds__(256) void wsum_kernel(
    const float* __restrict__ cls_w, const float* __restrict__ cls_b) {
    const int k  = (blockIdx.x & 7) * 256 + threadIdx.x;
    const int c0 = (blockIdx.x >> 3) * 40;
    float s = 0.0f;
#pragma unroll 8
    for (int c = c0; c < c0 + 40; c++) {
        float v = cls_w[(size_t)c * D_ + k];
        s += __bfloat162float(__float2bfloat16(v));   // match GEMM bf16 numerics
    }
    atomicAdd(&g_wsum[k], s);

    if (blockIdx.x == 0) {
        float bs = 0.0f;
        for (int i = threadIdx.x; i < C_; i += 256) bs += cls_b[i];
#pragma unroll
        for (int o = 16; o > 0; o >>= 1) bs += __shfl_xor_sync(~0u, bs, o);
        if ((threadIdx.x & 31) == 0) atomicAdd(&g_bsum, bs);
    }
}

// ---------------- kernel 2: cls_w -> bf16 ; zero loss ----------------
__global__ void prep_w_kernel(const float4* __restrict__ w,
                              float* __restrict__ loss_ptr) {
    int i = blockIdx.x * blockDim.x + threadIdx.x;
    float4 a = w[i];
    __nv_bfloat162 lo = __floats2bfloat162_rn(a.x, a.y);
    __nv_bfloat162 hi = __floats2bfloat162_rn(a.z, a.w);
    union { __nv_bfloat162 h[2]; uint2 u; } pk;
    pk.h[0] = lo; pk.h[1] = hi;
    reinterpret_cast<uint2*>(g_w)[i] = pk.u;
    if (i == 0 && loss_ptr) *loss_ptr = 0.0f;
}

// ---------------- kernel 3: z = feature+eps -> bf16 ; rowsum fused ----------
__global__ __launch_bounds__(256) void prep_z_kernel(
    const float4* __restrict__ f, const float4* __restrict__ e) {
    const int row = blockIdx.x;
    const int tid = threadIdx.x;
    const size_t b4 = (size_t)row * (D_ / 4);

    float partial = 0.0f;
#pragma unroll
    for (int j = 0; j < 2; j++) {
        const int idx = tid + j * 256;
        float4 a  = f[b4 + idx];
        float4 b  = e[b4 + idx];
        __nv_bfloat162 lo = __floats2bfloat162_rn(a.x + b.x, a.y + b.y);
        __nv_bfloat162 hi = __floats2bfloat162_rn(a.z + b.z, a.w + b.w);
        union { __nv_bfloat162 h[2]; uint2 u; } pk;
        pk.h[0] = lo; pk.h[1] = hi;
        reinterpret_cast<uint2*>(g_z)[b4 + idx] = pk.u;
        float4 ws = *reinterpret_cast<const float4*>(g_wsum + idx * 4);
        partial += __bfloat162float(lo.x) * ws.x + __bfloat162float(lo.y) * ws.y
                 + __bfloat162float(hi.x) * ws.z + __bfloat162float(hi.y) * ws.w;
    }
#pragma unroll
    for (int o = 16; o > 0; o >>= 1)
        partial += __shfl_xor_sync(~0u, partial, o);

    __shared__ float red[8];
    if ((tid & 31) == 0) red[tid >> 5] = partial;
    __syncthreads();
    if (tid == 0) {
        float t = 0.0f;
#pragma unroll
        for (int i = 0; i < 8; i++) t += red[i];
        g_rowsum[row] = t + g_bsum;
    }
}

// ============================================================================
// GEMM: logits = log(clamp((z @ w^T + cls_b) / rowsum)) fused, + loss
// CTA tile 128x128, BK=64, 3 stages. 128 threads = 4 warps (2m x 2n),
// warp tile 64x64. SMEM rows 128B (K=64 bf16), SW128 swizzled. occ 2.
// ============================================================================
#define BM 128
#define BN 128
#define BK 64
#define STAGES 3
#define NIT (D_ / BK)               // 32
#define STAGE_BYTES 32768           // A: 128*128 = 16384, B: 16384
#define SMEM_TOTAL (STAGES * STAGE_BYTES)   // 98304

#define SWZ128(o) ((o) ^ (((o) >> 3) & 0x70))

__device__ __forceinline__ uint32_t smem_u32(const void* p) {
    uint32_t a;
    asm("{ .reg .u64 t; cvta.to.shared.u64 t, %1; cvt.u32.u64 %0, t; }"
        : "=r"(a) : "l"(p));
    return a;
}
__device__ __forceinline__ void ldsm_x4(uint32_t r[4], uint32_t a) {
    asm volatile("ldmatrix.sync.aligned.m8n8.x4.shared.b16 {%0,%1,%2,%3}, [%4];"
                 : "=r"(r[0]), "=r"(r[1]), "=r"(r[2]), "=r"(r[3]) : "r"(a));
}
__device__ __forceinline__ void ldsm_x2(uint32_t r[2], uint32_t a) {
    asm volatile("ldmatrix.sync.aligned.m8n8.x2.shared.b16 {%0,%1}, [%2];"
                 : "=r"(r[0]), "=r"(r[1]) : "r"(a));
}
__device__ __forceinline__ void cpasync16(uint32_t dst, const void* src,
                                          uint32_t srcsz) {
    asm volatile("cp.async.cg.shared.global [%0], [%1], 16, %2;"
                 :: "r"(dst), "l"(src), "r"(srcsz));
}
__device__ __forceinline__ void mma16816(float c[4], const uint32_t a[4],
                                         uint32_t b0, uint32_t b1) {
    asm volatile(
        "mma.sync.aligned.m16n8k16.row.col.f32.bf16.bf16.f32 "
        "{%0,%1,%2,%3}, {%4,%5,%6,%7}, {%8,%9}, {%0,%1,%2,%3};\n"
        : "+f"(c[0]), "+f"(c[1]), "+f"(c[2]), "+f"(c[3])
        : "r"(a[0]), "r"(a[1]), "r"(a[2]), "r"(a[3]), "r"(b0), "r"(b1));
}

__global__ __launch_bounds__(128, 2) void gemm_kernel(
    const float* __restrict__ cls_b, const int* __restrict__ target,
    float* __restrict__ out, float* __restrict__ loss_ptr) {
    extern __shared__ char smem[];
    const uint32_t sb = smem_u32(smem);
    const int tid  = threadIdx.x;
    const int warp = tid >> 5;
    const int lane = tid & 31;
    const int wm   = warp >> 1;   // 0..1
    const int wn   = warp & 1;    // 0..1
    const int m0   = blockIdx.y * BM;
    const int n0   = blockIdx.x * BN;

    // re-zero wsum/bsum for next graph replay (read only by earlier kernels)
    if (blockIdx.x == 0 && blockIdx.y == 0) {
#pragma unroll
        for (int i = tid; i < D_; i += 128) g_wsum[i] = 0.0f;
        if (tid == 0) g_bsum = 0.0f;
    }

    // ---- cp.async mapping: row = (tid>>3) + 16*i, chunk = tid&7 ----
    const int rb  = tid >> 3;     // 0..15
    const int cb  = tid & 7;      // 16B chunk 0..7
    const __nv_bfloat16* a_base = &g_z[(size_t)(m0 + rb) * D_ + cb * 8];
    const int brow_base = n0 + rb;
    const uint32_t sw_dst = SWZ128(rb * 128 + cb * 16);

    // ---- ldmatrix per-lane offsets (within a stage) ----
    const int l15 = lane & 15;
    uint32_t aoff[4], boff[4];
#pragma unroll
    for (int kk = 0; kk < 4; kk++) {
        aoff[kk] = SWZ128((wm * 64 + l15) * 128 + (kk * 2 + (lane >> 4)) * 16);
        boff[kk] = 16384 +
            SWZ128((wn * 64 + (l15 & 7)) * 128 + (kk * 2 + ((l15 >> 3) & 1)) * 16);
    }

    float acc[4][8][4];
#pragma unroll
    for (int mi = 0; mi < 4; mi++)
#pragma unroll
        for (int ni = 0; ni < 8; ni++)
#pragma unroll
            for (int r = 0; r < 4; r++) acc[mi][ni][r] = 0.0f;

    auto issue_stage = [&](uint32_t so, int k0) {
#pragma unroll
        for (int i = 0; i < 8; i++) {
            cpasync16(sb + so + sw_dst + i * 2048,
                      a_base + (size_t)i * 16 * D_ + k0, 16u);
            const int brow = brow_base + i * 16;
            const int wr   = (brow < C_) ? brow : (C_ - 1);
            cpasync16(sb + so + 16384 + sw_dst + i * 2048,
                      &g_w[(size_t)wr * D_ + cb * 8 + k0],
                      (brow < C_) ? 16u : 0u);
        }
        asm volatile("cp.async.commit_group;" ::: "memory");
    };

    // ---- prologue: 2 stages in flight ----
    issue_stage(0, 0);
    issue_stage(STAGE_BYTES, BK);

    uint32_t so_c = 0;                     // compute stage offset
    uint32_t so_l = 2 * STAGE_BYTES;       // next load stage offset
    for (int it = 0; it < NIT; it++) {
        asm volatile("cp.async.wait_group 1;" ::: "memory");
        __syncthreads();

        if (it + 2 < NIT) {
            issue_stage(so_l, (it + 2) * BK);
        } else {
            asm volatile("cp.async.commit_group;" ::: "memory");
        }

        const uint32_t base = sb + so_c;
#pragma unroll
        for (int kk = 0; kk < 4; kk++) {
            uint32_t A[4][4];
#pragma unroll
            for (int mi = 0; mi < 4; mi++)
                ldsm_x4(A[mi], base + aoff[kk] + mi * 2048);   // +16 m-rows
            uint32_t Bf[8][2];
#pragma unroll
            for (int ni = 0; ni < 8; ni++)
                ldsm_x2(Bf[ni], base + boff[kk] + ni * 1024);  // +8 n-rows
#pragma unroll
            for (int mi = 0; mi < 4; mi++)
#pragma unroll
                for (int ni = 0; ni < 8; ni++)
                    mma16816(acc[mi][ni], A[mi], Bf[ni][0], Bf[ni][1]);
        }

        so_c += STAGE_BYTES; if (so_c == SMEM_TOTAL) so_c = 0;
        so_l += STAGE_BYTES; if (so_l == SMEM_TOTAL) so_l = 0;
    }

    // ---- fused epilogue: logits = log(clamp((acc+bias)/rowsum)) + loss ----
    const int g  = lane >> 2;
    const int tg = lane & 3;
#pragma unroll
    for (int mi = 0; mi < 4; mi++) {
        const int r0 = m0 + wm * 64 + mi * 16 + g;
        const int r1 = r0 + 8;
        const float inv0 = __fdividef(1.0f, g_rowsum[r0]);
        const float inv1 = __fdividef(1.0f, g_rowsum[r1]);
        const int t0 = target[r0];
        const int t1 = target[r1];
#pragma unroll
        for (int ni = 0; ni < 8; ni++) {
            const int col = n0 + wn * 64 + ni * 8 + tg * 2;
            if (col < C_) {   // C_ even -> col+1 valid too
                const float2 bb = *reinterpret_cast<const float2*>(cls_b + col);
                float p;
                float2 o0, o1;
                p = fminf(fmaxf((acc[mi][ni][0] + bb.x) * inv0, EPS32), 1.0f - EPS32);
                o0.x = __logf(p);
                p = fminf(fmaxf((acc[mi][ni][1] + bb.y) * inv0, EPS32), 1.0f - EPS32);
                o0.y = __logf(p);
                p = fminf(fmaxf((acc[mi][ni][2] + bb.x) * inv1, EPS32), 1.0f - EPS32);
                o1.x = __logf(p);
                p = fminf(fmaxf((acc[mi][ni][3] + bb.y) * inv1, EPS32), 1.0f - EPS32);
                o1.y = __logf(p);
                *reinterpret_cast<float2*>(out + (size_t)r0 * C_ + col) = o0;
                *reinterpret_cast<float2*>(out + (size_t)r1 * C_ + col) = o1;
                // loss = mean(gamma*rex + h3); gamma ~ 3.7e-44 makes gamma*rex
                // (~1e-40) vanish when added to h3 ~ 6.9 in fp32, so
                // loss == mean(-logits[b, target[b]]). Exactly one thread in
                // the grid matches each (row, target[row]) pair.
                if (loss_ptr) {
                    if (t0 == col)     atomicAdd(loss_ptr, -o0.x * (1.0f / (float)B_));
                    if (t0 == col + 1) atomicAdd(loss_ptr, -o0.y * (1.0f / (float)B_));
                    if (t1 == col)     atomicAdd(loss_ptr, -o1.x * (1.0f / (float)B_));
                    if (t1 == col + 1) atomicAdd(loss_ptr, -o1.y * (1.0f / (float)B_));
                }
            }
        }
    }
}

// ---------------- launch ----------------
extern "C" void kernel_launch(void* const* d_in, const int* in_sizes, int n_in,
                              void* d_out, int out_size) {
    const float* feature = (const float*)d_in[0];
    // d_in[1] = y_w, d_in[2] = y_b : unused (gamma*rex term vanishes in fp32)
    const float* cls_w   = (const float*)d_in[3];
    const float* cls_b   = (const float*)d_in[4];
    const float* eps     = (const float*)d_in[5];
    const int*   target  = (const int*)d_in[6];

    float* out = (float*)d_out;
    float* loss_ptr = (out_size >= B_ * C_ + 1) ? (out + (size_t)B_ * C_) : nullptr;

    cudaFuncSetAttribute(gemm_kernel,
                         cudaFuncAttributeMaxDynamicSharedMemorySize, SMEM_TOTAL);

    // 1) wsum[k] = sum_c bf16(w[c,k]) (fp32 source) ; bsum = sum(cls_b)
    wsum_kernel<<<200, 256>>>(cls_w, cls_b);

    // 2) cls_w -> bf16 ; zero loss accumulator
    prep_w_kernel<<<(C_ * D_ / 4) / 256, 256>>>((const float4*)cls_w, loss_ptr);

    // 3) z = feature + eps -> bf16 ; rowsum[b] = z.wsum + bsum (fused)
    prep_z_kernel<<<B_, 256>>>((const float4*)feature, (const float4*)eps);

    // 4) fused GEMM -> logits into d_out, loss accumulated; re-zeroes wsum/bsum
    dim3 grid((C_ + BN - 1) / BN, B_ / BM);   // 8 x 64 = 512 CTAs
    gemm_kernel<<<grid, 128, SMEM_TOTAL>>>(cls_b, target, out, loss_ptr);
}

// round 9
// speedup vs baseline: 1.0105x; 1.0105x over previous
#include <cuda_runtime.h>
#include <cuda_bf16.h>
#include <cstdint>

#define B_ 8192
#define D_ 2048
#define C_ 1000
#define EPS32 1.1920929e-7f

// ---------------- scratch (no allocations allowed) ----------------
__device__ __nv_bfloat16 g_z[B_ * (size_t)D_];   // z = feature + eps, bf16
__device__ __nv_bfloat16 g_w[C_ * (size_t)D_];   // cls_w, bf16 [C, D] K-major
__device__ float g_wsum[D_];                     // column sums of w (over C)
__device__ float g_bsum;                         // sum of cls_b
__device__ float g_rowsum[B_];                   // rowsum[b] = z.wsum + bsum

// NOTE: g_wsum / g_bsum are zero at module load; the GEMM kernel (last in the
// launch chain) re-zeroes them so graph replays stay correct.

// ---------------- kernel 1: wsum[k] = sum_c bf16(w[c,k]) ; bsum -------------
__global__ __launch_bounds__(256) void wsum_kernel(
    const float* __restrict__ cls_w, const float* __restrict__ cls_b) {
    const int k  = (blockIdx.x & 7) * 256 + threadIdx.x;
    const int c0 = (blockIdx.x >> 3) * 40;
    float s = 0.0f;
#pragma unroll 8
    for (int c = c0; c < c0 + 40; c++) {
        float v = cls_w[(size_t)c * D_ + k];
        s += __bfloat162float(__float2bfloat16(v));   // match GEMM bf16 numerics
    }
    atomicAdd(&g_wsum[k], s);

    if (blockIdx.x == 0) {
        float bs = 0.0f;
        for (int i = threadIdx.x; i < C_; i += 256) bs += cls_b[i];
#pragma unroll
        for (int o = 16; o > 0; o >>= 1) bs += __shfl_xor_sync(~0u, bs, o);
        if ((threadIdx.x & 31) == 0) atomicAdd(&g_bsum, bs);
    }
}

// ---------------- kernel 2: cls_w -> bf16 ; zero loss ----------------
__global__ void prep_w_kernel(const float4* __restrict__ w,
                              float* __restrict__ loss_ptr) {
    int i = blockIdx.x * blockDim.x + threadIdx.x;
    float4 a = w[i];
    __nv_bfloat162 lo = __floats2bfloat162_rn(a.x, a.y);
    __nv_bfloat162 hi = __floats2bfloat162_rn(a.z, a.w);
    union { __nv_bfloat162 h[2]; uint2 u; } pk;
    pk.h[0] = lo; pk.h[1] = hi;
    reinterpret_cast<uint2*>(g_w)[i] = pk.u;
    if (i == 0 && loss_ptr) *loss_ptr = 0.0f;
}

// ---------------- kernel 3: z = feature+eps -> bf16 ; rowsum fused ----------
__global__ __launch_bounds__(256) void prep_z_kernel(
    const float4* __restrict__ f, const float4* __restrict__ e) {
    const int row = blockIdx.x;
    const int tid = threadIdx.x;
    const size_t b4 = (size_t)row * (D_ / 4);

    float partial = 0.0f;
#pragma unroll
    for (int j = 0; j < 2; j++) {
        const int idx = tid + j * 256;
        float4 a  = f[b4 + idx];
        float4 b  = e[b4 + idx];
        __nv_bfloat162 lo = __floats2bfloat162_rn(a.x + b.x, a.y + b.y);
        __nv_bfloat162 hi = __floats2bfloat162_rn(a.z + b.z, a.w + b.w);
        union { __nv_bfloat162 h[2]; uint2 u; } pk;
        pk.h[0] = lo; pk.h[1] = hi;
        reinterpret_cast<uint2*>(g_z)[b4 + idx] = pk.u;
        float4 ws = *reinterpret_cast<const float4*>(g_wsum + idx * 4);
        partial += __bfloat162float(lo.x) * ws.x + __bfloat162float(lo.y) * ws.y
                 + __bfloat162float(hi.x) * ws.z + __bfloat162float(hi.y) * ws.w;
    }
#pragma unroll
    for (int o = 16; o > 0; o >>= 1)
        partial += __shfl_xor_sync(~0u, partial, o);

    __shared__ float red[8];
    if ((tid & 31) == 0) red[tid >> 5] = partial;
    __syncthreads();
    if (tid == 0) {
        float t = 0.0f;
#pragma unroll
        for (int i = 0; i < 8; i++) t += red[i];
        g_rowsum[row] = t + g_bsum;
    }
}

// ============================================================================
// GEMM: logits = log(clamp((z @ w^T + cls_b) / rowsum)) fused, + loss
// CTA tile 128x128, BK=32, 4 stages. 256 threads = 8 warps (2m x 4n),
// warp tile 64x32 -> 4 warps/SMSP at occ 2 for HMMA latency hiding.
// SMEM rows 64B (K=32 bf16), SW64 swizzled.
// ============================================================================
#define BM 128
#define BN 128
#define BK 32
#define STAGES 4
#define NIT (D_ / BK)               // 64
#define STAGE_BYTES 16384           // A: 128*64 = 8192, B: 8192
#define SMEM_TOTAL (STAGES * STAGE_BYTES)

#define SWZ64(o) ((o) ^ (((o) >> 3) & 0x30))

__device__ __forceinline__ uint32_t smem_u32(const void* p) {
    uint32_t a;
    asm("{ .reg .u64 t; cvta.to.shared.u64 t, %1; cvt.u32.u64 %0, t; }"
        : "=r"(a) : "l"(p));
    return a;
}
__device__ __forceinline__ void ldsm_x4(uint32_t r[4], uint32_t a) {
    asm volatile("ldmatrix.sync.aligned.m8n8.x4.shared.b16 {%0,%1,%2,%3}, [%4];"
                 : "=r"(r[0]), "=r"(r[1]), "=r"(r[2]), "=r"(r[3]) : "r"(a));
}
__device__ __forceinline__ void ldsm_x2(uint32_t r[2], uint32_t a) {
    asm volatile("ldmatrix.sync.aligned.m8n8.x2.shared.b16 {%0,%1}, [%2];"
                 : "=r"(r[0]), "=r"(r[1]) : "r"(a));
}
__device__ __forceinline__ void cpasync16(uint32_t dst, const void* src,
                                          uint32_t srcsz) {
    asm volatile("cp.async.cg.shared.global [%0], [%1], 16, %2;"
                 :: "r"(dst), "l"(src), "r"(srcsz));
}
__device__ __forceinline__ void mma16816(float c[4], const uint32_t a[4],
                                         uint32_t b0, uint32_t b1) {
    asm volatile(
        "mma.sync.aligned.m16n8k16.row.col.f32.bf16.bf16.f32 "
        "{%0,%1,%2,%3}, {%4,%5,%6,%7}, {%8,%9}, {%0,%1,%2,%3};\n"
        : "+f"(c[0]), "+f"(c[1]), "+f"(c[2]), "+f"(c[3])
        : "r"(a[0]), "r"(a[1]), "r"(a[2]), "r"(a[3]), "r"(b0), "r"(b1));
}

__global__ __launch_bounds__(256, 2) void gemm_kernel(
    const float* __restrict__ cls_b, const int* __restrict__ target,
    float* __restrict__ out, float* __restrict__ loss_ptr) {
    extern __shared__ char smem[];
    const uint32_t sb = smem_u32(smem);
    const int tid  = threadIdx.x;
    const int warp = tid >> 5;
    const int lane = tid & 31;
    const int wm   = warp >> 2;   // 0..1  (64 m-rows each)
    const int wn   = warp & 3;    // 0..3  (32 n-cols each)
    const int m0   = blockIdx.y * BM;
    const int n0   = blockIdx.x * BN;

    // re-zero wsum/bsum for next graph replay (read only by earlier kernels)
    if (blockIdx.x == 0 && blockIdx.y == 0) {
        for (int i = tid; i < D_; i += 256) g_wsum[i] = 0.0f;
        if (tid == 0) g_bsum = 0.0f;
    }

    // ---- cp.async mapping: 16B/thread, rows lrow and lrow+64 ----
    const int lrow = tid >> 2;          // 0..63
    const int lchk = tid & 3;           // chunk 0..3
    const __nv_bfloat16* asrc0 = &g_z[(size_t)(m0 + lrow) * D_ + lchk * 8];
    const __nv_bfloat16* asrc1 = asrc0 + (size_t)64 * D_;
    const uint32_t adst0 = sb + SWZ64(lrow * 64 + lchk * 16);
    const uint32_t adst1 = sb + SWZ64((lrow + 64) * 64 + lchk * 16);
    const int br0 = n0 + lrow, br1 = n0 + lrow + 64;
    const uint32_t bsz0 = (br0 < C_) ? 16u : 0u;
    const uint32_t bsz1 = (br1 < C_) ? 16u : 0u;
    const __nv_bfloat16* bsrc0 = &g_w[(size_t)((br0 < C_) ? br0 : (C_ - 1)) * D_ + lchk * 8];
    const __nv_bfloat16* bsrc1 = &g_w[(size_t)((br1 < C_) ? br1 : (C_ - 1)) * D_ + lchk * 8];
    const uint32_t bdst0 = sb + 8192 + SWZ64(lrow * 64 + lchk * 16);
    const uint32_t bdst1 = sb + 8192 + SWZ64((lrow + 64) * 64 + lchk * 16);

    // ---- ldmatrix per-lane offsets (within a stage) ----
    const int l15 = lane & 15;
    uint32_t aoff[2], boff[2];
#pragma unroll
    for (int kk = 0; kk < 2; kk++) {
        const int achunk = kk * 2 + (lane >> 4);
        aoff[kk] = SWZ64((wm * 64 + l15) * 64 + achunk * 16);
        const int bchunk = kk * 2 + ((l15 >> 3) & 1);
        boff[kk] = 8192 + SWZ64((wn * 32 + (l15 & 7)) * 64 + bchunk * 16);
    }

    float acc[4][4][4];
#pragma unroll
    for (int mi = 0; mi < 4; mi++)
#pragma unroll
        for (int ni = 0; ni < 4; ni++)
#pragma unroll
            for (int r = 0; r < 4; r++) acc[mi][ni][r] = 0.0f;

    // ---- prologue: 3 stages in flight ----
#pragma unroll
    for (int s = 0; s < STAGES - 1; s++) {
        const uint32_t so = s * STAGE_BYTES;
        const int k0 = s * BK;
        cpasync16(adst0 + so, asrc0 + k0, 16u);
        cpasync16(adst1 + so, asrc1 + k0, 16u);
        cpasync16(bdst0 + so, bsrc0 + k0, bsz0);
        cpasync16(bdst1 + so, bsrc1 + k0, bsz1);
        asm volatile("cp.async.commit_group;" ::: "memory");
    }

    for (int it = 0; it < NIT; it++) {
        asm volatile("cp.async.wait_group 2;" ::: "memory");
        __syncthreads();

        if (it + STAGES - 1 < NIT) {
            const uint32_t so = ((it + STAGES - 1) & 3) * STAGE_BYTES;
            const int k0 = (it + STAGES - 1) * BK;
            cpasync16(adst0 + so, asrc0 + k0, 16u);
            cpasync16(adst1 + so, asrc1 + k0, 16u);
            cpasync16(bdst0 + so, bsrc0 + k0, bsz0);
            cpasync16(bdst1 + so, bsrc1 + k0, bsz1);
        }
        asm volatile("cp.async.commit_group;" ::: "memory");

        const uint32_t base = sb + (it & 3) * STAGE_BYTES;
#pragma unroll
        for (int kk = 0; kk < 2; kk++) {
            uint32_t A[4][4];
#pragma unroll
            for (int mi = 0; mi < 4; mi++)
                ldsm_x4(A[mi], base + aoff[kk] + mi * 1024);   // +16 m-rows
            uint32_t Bf[4][2];
#pragma unroll
            for (int ni = 0; ni < 4; ni++)
                ldsm_x2(Bf[ni], base + boff[kk] + ni * 512);   // +8 n-rows
#pragma unroll
            for (int mi = 0; mi < 4; mi++)
#pragma unroll
                for (int ni = 0; ni < 4; ni++)
                    mma16816(acc[mi][ni], A[mi], Bf[ni][0], Bf[ni][1]);
        }
    }

    // ---- fused epilogue: logits = log(clamp((acc+bias)/rowsum)) + loss ----
    const int g  = lane >> 2;
    const int tg = lane & 3;
#pragma unroll
    for (int mi = 0; mi < 4; mi++) {
        const int r0 = m0 + wm * 64 + mi * 16 + g;
        const int r1 = r0 + 8;
        const float inv0 = __fdividef(1.0f, g_rowsum[r0]);
        const float inv1 = __fdividef(1.0f, g_rowsum[r1]);
        const int t0 = target[r0];
        const int t1 = target[r1];
#pragma unroll
        for (int ni = 0; ni < 4; ni++) {
            const int col = n0 + wn * 32 + ni * 8 + tg * 2;
            if (col < C_) {   // C_ even -> col+1 valid too
                const float2 bb = *reinterpret_cast<const float2*>(cls_b + col);
                float p;
                float2 o0, o1;
                p = fminf(fmaxf((acc[mi][ni][0] + bb.x) * inv0, EPS32), 1.0f - EPS32);
                o0.x = __logf(p);
                p = fminf(fmaxf((acc[mi][ni][1] + bb.y) * inv0, EPS32), 1.0f - EPS32);
                o0.y = __logf(p);
                p = fminf(fmaxf((acc[mi][ni][2] + bb.x) * inv1, EPS32), 1.0f - EPS32);
                o1.x = __logf(p);
                p = fminf(fmaxf((acc[mi][ni][3] + bb.y) * inv1, EPS32), 1.0f - EPS32);
                o1.y = __logf(p);
                *reinterpret_cast<float2*>(out + (size_t)r0 * C_ + col) = o0;
                *reinterpret_cast<float2*>(out + (size_t)r1 * C_ + col) = o1;
                // loss = mean(gamma*rex + h3); gamma ~ 3.7e-44 makes gamma*rex
                // (~1e-40) vanish when added to h3 ~ 6.9 in fp32, so
                // loss == mean(-logits[b, target[b]]). Exactly one thread in
                // the grid matches each (row, target[row]) pair.
                if (loss_ptr) {
                    if (t0 == col)     atomicAdd(loss_ptr, -o0.x * (1.0f / (float)B_));
                    if (t0 == col + 1) atomicAdd(loss_ptr, -o0.y * (1.0f / (float)B_));
                    if (t1 == col)     atomicAdd(loss_ptr, -o1.x * (1.0f / (float)B_));
                    if (t1 == col + 1) atomicAdd(loss_ptr, -o1.y * (1.0f / (float)B_));
                }
            }
        }
    }
}

// ---------------- launch ----------------
extern "C" void kernel_launch(void* const* d_in, const int* in_sizes, int n_in,
                              void* d_out, int out_size) {
    const float* feature = (const float*)d_in[0];
    // d_in[1] = y_w, d_in[2] = y_b : unused (gamma*rex term vanishes in fp32)
    const float* cls_w   = (const float*)d_in[3];
    const float* cls_b   = (const float*)d_in[4];
    const float* eps     = (const float*)d_in[5];
    const int*   target  = (const int*)d_in[6];

    float* out = (float*)d_out;
    float* loss_ptr = (out_size >= B_ * C_ + 1) ? (out + (size_t)B_ * C_) : nullptr;

    cudaFuncSetAttribute(gemm_kernel,
                         cudaFuncAttributeMaxDynamicSharedMemorySize, SMEM_TOTAL);

    // 1) wsum[k] = sum_c bf16(w[c,k]) (fp32 source) ; bsum = sum(cls_b)
    wsum_kernel<<<200, 256>>>(cls_w, cls_b);

    // 2) cls_w -> bf16 ; zero loss accumulator
    prep_w_kernel<<<(C_ * D_ / 4) / 256, 256>>>((const float4*)cls_w, loss_ptr);

    // 3) z = feature + eps -> bf16 ; rowsum[b] = z.wsum + bsum (fused)
    prep_z_kernel<<<B_, 256>>>((const float4*)feature, (const float4*)eps);

    // 4) fused GEMM -> logits into d_out, loss accumulated; re-zeroes wsum/bsum
    dim3 grid((C_ + BN - 1) / BN, B_ / BM);   // 8 x 64 = 512 CTAs
    gemm_kernel<<<grid, 256, SMEM_TOTAL>>>(cls_b, target, out, loss_ptr);
}